// round 17
// baseline (speedup 1.0000x reference)
#include <cuda_runtime.h>
#include <cuda_fp16.h>

// Swin window attention, fused per 8x8 window — fp16 tensor cores (m16n8k16).
// R17: A-operands register-resident. Each warp loads its 16x192 A-strip once
// (48 fragment regs) and reuses it across all 6 heads (phase 1) and both proj
// chunks (phase 3), cutting phase-1 A-LDS traffic 6x. Weights remain
// fragment-major fp16 in __device__ globals (L2-resident), 2 CTAs/SM.

#define BATCH 4
#define IMGH  256
#define IMGW  256
#define CH    192
#define NHEAD 6
#define HDIM  32

#define SXS 200   // row stride (halfs) for sx/sout, sq, sk
#define VTS 72    // row stride (halfs) for v-transposed

// smem byte offsets
#define SX_OFF   0         // 64*200*2 = 25600 (x, later attention output)
#define SQ_OFF   25600     // 64*200*2 = 25600 (q all heads, col h*32)
#define SK_OFF   51200     // 64*200*2 = 25600 (k all heads, col h*32)
#define SVT_OFF  76800     // 192*72*2 = 27648 (v^T all heads, row h*32+d)
#define SBQ_OFF  104448    // 576*4
#define SBP_OFF  106752    // 192*4
#define SMEM_BYTES 107520

// fragment-major weights: frag id = ((chunk*12 + jglob)*12 + ks), 32 lanes each
#define QKV_FRAGS  (6*12*12*32)   // 27648
#define PROJ_FRAGS (2*12*12*32)   // 9216
__device__ uint2 d_qkv_wf[QKV_FRAGS];
__device__ uint2 d_proj_wf[PROJ_FRAGS];

__device__ __forceinline__ unsigned pk(float lo, float hi) {
    __half2 h = __floats2half2_rn(lo, hi);
    return *reinterpret_cast<unsigned*>(&h);
}
__device__ __forceinline__ unsigned ldu(const __half* p) {
    return *reinterpret_cast<const unsigned*>(p);
}
__device__ __forceinline__ void mma16(float* d, const unsigned* a, unsigned b0, unsigned b1) {
    asm volatile(
        "mma.sync.aligned.m16n8k16.row.col.f32.f16.f16.f32 "
        "{%0,%1,%2,%3}, {%4,%5,%6,%7}, {%8,%9}, {%0,%1,%2,%3};"
        : "+f"(d[0]), "+f"(d[1]), "+f"(d[2]), "+f"(d[3])
        : "r"(a[0]), "r"(a[1]), "r"(a[2]), "r"(a[3]), "r"(b0), "r"(b1));
}

// ---- prep: pack weights into fragment-major fp16 (one LDG.64 per lane) ----
__global__ void prep_weights(const float* __restrict__ qkv_w,
                             const float* __restrict__ proj_w)
{
    const int idx = blockIdx.x * 256 + threadIdx.x;
    if (idx < QKV_FRAGS) {
        const int lane = idx & 31;
        const int g  = lane >> 2, lc = lane & 3;
        int rest = idx >> 5;
        const int ks = rest % 12; rest /= 12;
        const int j  = rest % 12; rest /= 12;
        const int c  = rest;                   // head chunk 0..5
        const int n  = 8*j + g;                // 0..95 within chunk
        const int gr = (n < 32) ? (c*32 + n)
                     : (n < 64) ? (CH + c*32 + (n - 32))
                                : (2*CH + c*32 + (n - 64));
        const float* wr = qkv_w + gr*CH + ks*16 + 2*lc;
        d_qkv_wf[idx] = make_uint2(pk(wr[0], wr[1]), pk(wr[8], wr[9]));
    } else if (idx < QKV_FRAGS + PROJ_FRAGS) {
        const int p = idx - QKV_FRAGS;
        const int lane = p & 31;
        const int g  = lane >> 2, lc = lane & 3;
        int rest = p >> 5;
        const int ks = rest % 12; rest /= 12;
        const int j  = rest % 12; rest /= 12;
        const int chunk = rest;                // 0..1
        const int gr = chunk*96 + 8*j + g;
        const float* wr = proj_w + gr*CH + ks*16 + 2*lc;
        d_proj_wf[p] = make_uint2(pk(wr[0], wr[1]), pk(wr[8], wr[9]));
    }
}

__global__ __launch_bounds__(384, 2)
void win_attn_kernel(const float* __restrict__ x,
                     const float* __restrict__ qkv_b,   // [576]
                     const float* __restrict__ proj_b,  // [192]
                     const float* __restrict__ bias,    // [6,64,64]
                     float* __restrict__ out)
{
    extern __shared__ char smem[];
    __half* sx  = (__half*)(smem + SX_OFF);    // 64 x SXS (x, later sout)
    __half* sq  = (__half*)(smem + SQ_OFF);    // 64 x SXS, head h at col h*32
    __half* sk  = (__half*)(smem + SK_OFF);    // 64 x SXS, head h at col h*32
    __half* svt = (__half*)(smem + SVT_OFF);   // 192 x VTS, [h*32+d][token]
    float*  sbq = (float*)(smem + SBQ_OFF);
    float*  sbp = (float*)(smem + SBP_OFF);

    const int tid  = threadIdx.x;
    const int warp = tid >> 5;        // 0..11
    const int lane = tid & 31;
    const int g    = lane >> 2;       // 0..7
    const int lc   = lane & 3;        // 0..3
    const int mw   = warp & 3;        // m strip 0..3
    const int nwt  = warp >> 2;       // n group 0..2
    const int m0   = mw * 16;

    const int w  = blockIdx.x;
    const int b  = w >> 10;
    const int wh = (w >> 5) & 31;
    const int ww = w & 31;
    const long long base = ((long long)b * (IMGH*IMGW) + (long long)(wh*8)*IMGW + (ww*8)) * CH;

    // ---- gather x -> fp16 sx; biases -> smem ----
    for (int i = tid; i < 64*48; i += 384) {
        const int t  = i / 48;
        const int c4 = i % 48;
        const long long ga = base + (long long)(t >> 3) * (IMGW*CH) + (t & 7) * CH + c4*4;
        float4 v = *(const float4*)(x + ga);
        *(uint2*)(sx + t*SXS + c4*4) = make_uint2(pk(v.x, v.y), pk(v.z, v.w));
    }
    for (int i = tid; i < 576; i += 384) sbq[i] = qkv_b[i];
    if (tid < 192) sbp[tid] = proj_b[tid];
    __syncthreads();

    const float scale = 0.17677669529663687f; // 1/sqrt(32)

    // ================= phase 1: QKV, all heads; A register-resident ==========
    {
        // load this warp's 16x192 A-strip once: 48 fragment regs
        unsigned A[48];
        {
            const __half* a0 = sx + (m0 + g)*SXS + 2*lc;
            #pragma unroll
            for (int ks = 0; ks < 12; ++ks) {
                A[4*ks+0] = ldu(a0 + 16*ks);
                A[4*ks+1] = ldu(a0 + 8*SXS + 16*ks);
                A[4*ks+2] = ldu(a0 + 16*ks + 8);
                A[4*ks+3] = ldu(a0 + 8*SXS + 16*ks + 8);
            }
        }

        for (int c = 0; c < NHEAD; ++c) {
            const uint2* wfb = d_qkv_wf + ((c*12 + nwt*4)*12)*32 + lane;
            const int r0 = m0 + g;

            #pragma unroll
            for (int j = 0; j < 4; ++j) {
                float acc[4] = {0.f, 0.f, 0.f, 0.f};
                const uint2* wfj = wfb + (j*12)*32;
                #pragma unroll
                for (int ks = 0; ks < 12; ++ks) {
                    const uint2 bb = __ldg(wfj + ks*32);
                    mma16(acc, A + 4*ks, bb.x, bb.y);
                }

                // epilogue: warp-specialized scatter (nwt: 0->q, 1->k, 2->v)
                const int n = 8*j + 2*lc;
                if (nwt == 0) {                   // q, pre-scaled
                    const float b0 = sbq[c*32 + n], b1 = sbq[c*32 + n + 1];
                    *(unsigned*)(sq + r0*SXS + c*32 + n) =
                        pk((acc[0]+b0)*scale, (acc[1]+b1)*scale);
                    *(unsigned*)(sq + (r0+8)*SXS + c*32 + n) =
                        pk((acc[2]+b0)*scale, (acc[3]+b1)*scale);
                } else if (nwt == 1) {            // k
                    const float b0 = sbq[CH + c*32 + n], b1 = sbq[CH + c*32 + n + 1];
                    *(unsigned*)(sk + r0*SXS + c*32 + n) = pk(acc[0]+b0, acc[1]+b1);
                    *(unsigned*)(sk + (r0+8)*SXS + c*32 + n) = pk(acc[2]+b0, acc[3]+b1);
                } else {                          // v transposed [h*32+d][token]
                    const float b0 = sbq[2*CH + c*32 + n], b1 = sbq[2*CH + c*32 + n + 1];
                    __half* vb = svt + (c*32 + n)*VTS;
                    vb[r0]           = __float2half_rn(acc[0] + b0);
                    vb[VTS + r0]     = __float2half_rn(acc[1] + b1);
                    vb[r0 + 8]       = __float2half_rn(acc[2] + b0);
                    vb[VTS + r0 + 8] = __float2half_rn(acc[3] + b1);
                }
            }
        }
    }
    __syncthreads();

    // ================= phase 2: attention, 24 warp-tasks, 2 per warp =========
    #pragma unroll 1
    for (int rep = 0; rep < 2; ++rep) {
        const int task = warp + 12*rep;       // 0..23
        const int h    = task >> 2;
        const int sm0  = (task & 3) * 16;

        // scores m16 x n64, K=32
        float acc[8][4];
        #pragma unroll
        for (int j = 0; j < 8; ++j)
            #pragma unroll
            for (int i = 0; i < 4; ++i) acc[j][i] = 0.f;

        const __half* aq = sq + (sm0 + g)*SXS + h*HDIM + 2*lc;
        #pragma unroll
        for (int kk = 0; kk < 2; ++kk) {
            const int k0 = kk * 16;
            unsigned a[4];
            a[0] = ldu(aq + k0);       a[1] = ldu(aq + 8*SXS + k0);
            a[2] = ldu(aq + k0 + 8);   a[3] = ldu(aq + 8*SXS + k0 + 8);
            #pragma unroll
            for (int j = 0; j < 8; ++j) {
                const __half* bkp = sk + (8*j + g)*SXS + h*HDIM + 2*lc + k0;
                mma16(acc[j], a, ldu(bkp), ldu(bkp + 8));
            }
        }

        // + bias (L2-resident LDG), register softmax
        const float* bp = bias + h*4096 + (sm0 + g)*64 + 2*lc;
        float mx0 = -1e30f, mx1 = -1e30f;
        #pragma unroll
        for (int j = 0; j < 8; ++j) {
            const float2 bA = *(const float2*)(bp + 8*j);
            const float2 bB = *(const float2*)(bp + 512 + 8*j);
            acc[j][0] += bA.x; acc[j][1] += bA.y;
            acc[j][2] += bB.x; acc[j][3] += bB.y;
            mx0 = fmaxf(mx0, fmaxf(acc[j][0], acc[j][1]));
            mx1 = fmaxf(mx1, fmaxf(acc[j][2], acc[j][3]));
        }
        mx0 = fmaxf(mx0, __shfl_xor_sync(0xffffffffu, mx0, 1));
        mx0 = fmaxf(mx0, __shfl_xor_sync(0xffffffffu, mx0, 2));
        mx1 = fmaxf(mx1, __shfl_xor_sync(0xffffffffu, mx1, 1));
        mx1 = fmaxf(mx1, __shfl_xor_sync(0xffffffffu, mx1, 2));
        float s0 = 0.f, s1 = 0.f;
        #pragma unroll
        for (int j = 0; j < 8; ++j) {
            acc[j][0] = __expf(acc[j][0] - mx0); acc[j][1] = __expf(acc[j][1] - mx0);
            acc[j][2] = __expf(acc[j][2] - mx1); acc[j][3] = __expf(acc[j][3] - mx1);
            s0 += acc[j][0] + acc[j][1];
            s1 += acc[j][2] + acc[j][3];
        }
        s0 += __shfl_xor_sync(0xffffffffu, s0, 1);
        s0 += __shfl_xor_sync(0xffffffffu, s0, 2);
        s1 += __shfl_xor_sync(0xffffffffu, s1, 1);
        s1 += __shfl_xor_sync(0xffffffffu, s1, 2);
        const float inv0 = 1.0f / s0, inv1 = 1.0f / s1;

        // pack probs: D-fragment layout == A-fragment layout for P@V
        unsigned pa[8], pb[8];
        #pragma unroll
        for (int j = 0; j < 8; ++j) {
            pa[j] = pk(acc[j][0]*inv0, acc[j][1]*inv0);
            pb[j] = pk(acc[j][2]*inv1, acc[j][3]*inv1);
        }

        // out_h m16 x n32, K=64; B = v^T
        float oacc[4][4];
        #pragma unroll
        for (int j = 0; j < 4; ++j)
            #pragma unroll
            for (int i = 0; i < 4; ++i) oacc[j][i] = 0.f;
        #pragma unroll
        for (int kk = 0; kk < 4; ++kk) {
            unsigned a[4] = { pa[2*kk], pb[2*kk], pa[2*kk+1], pb[2*kk+1] };
            #pragma unroll
            for (int jj = 0; jj < 4; ++jj) {
                const __half* bvp = svt + (h*HDIM + 8*jj + g)*VTS + 2*lc + 16*kk;
                mma16(oacc[jj], a, ldu(bvp), ldu(bvp + 8));
            }
        }

        // write attention output into sx (cols h*32..)
        __half* so = sx + (sm0 + g)*SXS + h*HDIM;
        #pragma unroll
        for (int jj = 0; jj < 4; ++jj) {
            const int cc = 8*jj + 2*lc;
            *(unsigned*)(so + cc)         = pk(oacc[jj][0], oacc[jj][1]);
            *(unsigned*)(so + 8*SXS + cc) = pk(oacc[jj][2], oacc[jj][3]);
        }
    }
    __syncthreads();

    // ================= phase 3: projection; A register-resident ==============
    {
        unsigned A[48];
        {
            const __half* a0 = sx + (m0 + g)*SXS + 2*lc;   // attention output
            #pragma unroll
            for (int ks = 0; ks < 12; ++ks) {
                A[4*ks+0] = ldu(a0 + 16*ks);
                A[4*ks+1] = ldu(a0 + 8*SXS + 16*ks);
                A[4*ks+2] = ldu(a0 + 16*ks + 8);
                A[4*ks+3] = ldu(a0 + 8*SXS + 16*ks + 8);
            }
        }

        const int t0 = m0 + g;
        const int t1 = t0 + 8;
        const long long ga0 = base + (long long)(t0 >> 3) * (IMGW*CH) + (t0 & 7) * CH;
        const long long ga1 = base + (long long)(t1 >> 3) * (IMGW*CH) + (t1 & 7) * CH;

        #pragma unroll 1
        for (int chunk = 0; chunk < 2; ++chunk) {
            const uint2* wfb = d_proj_wf + ((chunk*12 + nwt*4)*12)*32 + lane;
            #pragma unroll
            for (int j = 0; j < 4; ++j) {
                float acc[4] = {0.f, 0.f, 0.f, 0.f};
                const uint2* wfj = wfb + (j*12)*32;
                #pragma unroll
                for (int ks = 0; ks < 12; ++ks) {
                    const uint2 bb = __ldg(wfj + ks*32);
                    mma16(acc, A + 4*ks, bb.x, bb.y);
                }
                const int n = chunk*96 + nwt*32 + 8*j + 2*lc;
                const float b0 = sbp[n], b1 = sbp[n + 1];
                *(float2*)(out + ga0 + n) = make_float2(acc[0] + b0, acc[1] + b1);
                *(float2*)(out + ga1 + n) = make_float2(acc[2] + b0, acc[3] + b1);
            }
        }
    }
}

extern "C" void kernel_launch(void* const* d_in, const int* in_sizes, int n_in,
                              void* d_out, int out_size)
{
    const float* x      = (const float*)d_in[0];
    const float* qkv_w  = (const float*)d_in[1];
    const float* qkv_b  = (const float*)d_in[2];
    const float* proj_w = (const float*)d_in[3];
    const float* proj_b = (const float*)d_in[4];
    const float* bias   = (const float*)d_in[5];
    float* out = (float*)d_out;

    cudaFuncSetAttribute(win_attn_kernel,
                         cudaFuncAttributeMaxDynamicSharedMemorySize, SMEM_BYTES);

    prep_weights<<<(QKV_FRAGS + PROJ_FRAGS + 255) / 256, 256>>>(qkv_w, proj_w);

    const int n_windows = BATCH * (IMGH/8) * (IMGW/8);   // 4096
    win_attn_kernel<<<n_windows, 384, SMEM_BYTES>>>(x, qkv_b, proj_b, bias, out);
}